// round 11
// baseline (speedup 1.0000x reference)
#include <cuda_runtime.h>
#include <cstdint>

// ImprovedVectorizationLoss: fused masked-L1 + BCE + continuity + recon-MSE.
// Persistent work-stealing kernel (740 blocks, 5/SM). Segments of 512 records
// claimed via atomic counter; next-segment cp.async prefetch overlaps
// continuity; recon-MSE iterations are interleaved one-per-tile-compute so
// every compute phase has independent LDG traffic in flight.

#define M_ROW 4096
#define TPB   256
#define SEGS  8
#define SEG   (M_ROW / SEGS)         // 512
#define TILE  256
#define NTILE (SEG / TILE)           // 2
#define NF4T  (TILE * 9 / 4)         // 576 float4 per tile per tensor
#define NBLOCKS 740                  // 5 blocks/SM x 148 SMs, single wave
#define BMAX  512
#define EPSV  1e-7f

__device__ float        g_acc[6];                  // [coord,width,bce,nvalid,cont,recon]
__device__ unsigned int g_ticket;
__device__ unsigned int g_work;                    // segment work counter
__device__ int          g_first_idx[BMAX * SEGS];
__device__ float2       g_first_p45[BMAX * SEGS];
__device__ float2       g_last_p45[BMAX * SEGS];

__device__ __forceinline__ float warpReduceSumF(float v) {
#pragma unroll
    for (int o = 16; o > 0; o >>= 1) v += __shfl_down_sync(0xffffffffu, v, o);
    return v;
}

__device__ __forceinline__ void cp16(void* s, const void* g) {
    unsigned saddr = (unsigned)__cvta_generic_to_shared(s);
    asm volatile("cp.async.cg.shared.global [%0], [%1], 16;" :: "r"(saddr), "l"(g));
}
#define CP_COMMIT() asm volatile("cp.async.commit_group;")
#define CP_WAIT(n)  asm volatile("cp.async.wait_group %0;" :: "n"(n))

__global__ __launch_bounds__(TPB, 5) void loss_fused_kernel(
    const float* __restrict__ preds, const float* __restrict__ tgts,
    const float* __restrict__ rec,   const float* __restrict__ img,
    float* __restrict__ out, int B, int nrec)
{
    __shared__ float    sp[NTILE * TILE * 9];   // 18 KB
    __shared__ float    st[NTILE * TILE * 9];   // 18 KB
    __shared__ float2   s45f[SEG];              // 4 KB
    __shared__ unsigned smask[16];
    __shared__ float    swred[6][8];
    __shared__ int      s_seg;                  // next stolen segment
    __shared__ int      slast;

    const int tid  = threadIdx.x;
    const int bid  = blockIdx.x;
    const int lane = tid & 31;
    const int wid  = tid >> 5;
    const int NSEG = B * SEGS;

    float coordS = 0.f, widthS = 0.f, bceS = 0.f, nvS = 0.f, contS = 0.f, reconS = 0.f;

    // recon cursor (grid-stride order, advanced throughout the kernel)
    const float4* r4 = reinterpret_cast<const float4*>(rec);
    const float4* i4 = reinterpret_cast<const float4*>(img);
    const int n4 = nrec >> 2;
    int rcur = bid * TPB + tid;
    const int rstep = NBLOCKS * TPB;

    // ---- prologue: steal first segment, start its prefetch ----
    if (tid == 0) s_seg = (int)atomicAdd(&g_work, 1u);
    __syncthreads();
    int s0 = s_seg;

    if (s0 < NSEG) {
        const float4* p4 = reinterpret_cast<const float4*>(preds + (size_t)s0 * SEG * 9);
        const float4* t4 = reinterpret_cast<const float4*>(tgts  + (size_t)s0 * SEG * 9);
#pragma unroll
        for (int tl = 0; tl < NTILE; tl++) {
            float4* spd = reinterpret_cast<float4*>(sp) + tl * NF4T;
            float4* std_ = reinterpret_cast<float4*>(st) + tl * NF4T;
            for (int i = tid; i < NF4T; i += TPB) {
                cp16(&spd[i], &p4[tl * NF4T + i]);
                cp16(&std_[i], &t4[tl * NF4T + i]);
            }
            CP_COMMIT();
        }
    }

    // ---- two recon iterations cover the first prefetch latency ----
#pragma unroll
    for (int k = 0; k < 2; k++) {
        if (rcur < n4) {
            float4 r = r4[rcur], m = i4[rcur];
            float dx = r.x - m.x, dy = r.y - m.y, dz = r.z - m.z, dw = r.w - m.w;
            reconS += dx * dx + dy * dy + dz * dz + dw * dw;
            rcur += rstep;
        }
    }

    // ---- persistent segment loop ----
    while (s0 < NSEG) {
        if (tid == 0) s_seg = (int)atomicAdd(&g_work, 1u);

        unsigned v0 = 0u, v1 = 0u;
        float2   q45[2];
#pragma unroll
        for (int tile = 0; tile < NTILE; tile++) {
            if (tile == 0) CP_WAIT(1); else CP_WAIT(0);
            __syncthreads();   // tile data visible (also publishes s_seg)

            // interleaved recon iteration: independent LDGs in flight
            // while the record LDS/FLOP chain executes below.
            float4 rr, mm;
            bool rdo = (rcur < n4);
            if (rdo) { rr = r4[rcur]; mm = i4[rcur]; rcur += rstep; }

            const float* pr = sp + (tile * TILE + tid) * 9;
            const float* tr = st + (tile * TILE + tid) * 9;
            float t8   = tr[8];
            float mask = (t8 > 0.5f) ? 1.0f : 0.0f;
            if (tile == 0) v0 = (t8 > 0.5f) ? 1u : 0u;
            else           v1 = (t8 > 0.5f) ? 1u : 0u;

            float a4 = pr[4], a5 = pr[5];
            coordS += (fabsf(pr[0] - tr[0]) + fabsf(pr[1] - tr[1]) + fabsf(pr[2] - tr[2])
                     + fabsf(pr[3] - tr[3]) + fabsf(a4 - tr[4]) + fabsf(a5 - tr[5])) * mask;
            widthS += (fabsf(pr[6] - tr[6]) + fabsf(pr[7] - tr[7])) * mask;

            float p = fminf(fmaxf(pr[8], EPSV), 1.0f - EPSV);
            bceS   += -(t8 * __logf(p) + (1.0f - t8) * __logf(1.0f - p));
            nvS    += mask;

            q45[tile] = make_float2(a4, a5);
            s45f[tile * TILE + tid] = q45[tile];

            if (rdo) {
                float dx = rr.x - mm.x, dy = rr.y - mm.y, dz = rr.z - mm.z, dw = rr.w - mm.w;
                reconS += dx * dx + dy * dy + dz * dz + dw * dw;
            }
        }
        {
            unsigned b0 = __ballot_sync(0xffffffffu, v0 != 0u);
            unsigned b1 = __ballot_sync(0xffffffffu, v1 != 0u);
            if (lane == 0) { smask[wid] = b0; smask[8 + wid] = b1; }
        }
        __syncthreads();   // sp/st consumed; s45f + masks visible

        const int s1 = s_seg;

        // ---- prefetch next segment into the freed buffers ----
        if (s1 < NSEG) {
            const float4* p4 = reinterpret_cast<const float4*>(preds + (size_t)s1 * SEG * 9);
            const float4* t4 = reinterpret_cast<const float4*>(tgts  + (size_t)s1 * SEG * 9);
#pragma unroll
            for (int tl = 0; tl < NTILE; tl++) {
                float4* spd = reinterpret_cast<float4*>(sp) + tl * NF4T;
                float4* std_ = reinterpret_cast<float4*>(st) + tl * NF4T;
                for (int i = tid; i < NF4T; i += TPB) {
                    cp16(&spd[i], &p4[tl * NF4T + i]);
                    cp16(&std_[i], &t4[tl * NF4T + i]);
                }
                CP_COMMIT();
            }
        }

        // ---- continuity of s0 runs under the prefetch ----
        const int rs = s0;
#pragma unroll
        for (int t = 0; t < 2; t++) {
            unsigned vv = t ? v1 : v0;
            if (vv) {
                const int j = t * TILE + tid;
                const int k = j >> 5;
                unsigned rem = (lane < 31) ? (smask[k] & (0xFFFFFFFEu << lane)) : 0u;
                int k2 = k;
                while (rem == 0u && ++k2 < 16) rem = smask[k2];
                float2 a = q45[t];
                if (rem != 0u) {
                    int nxt = (k2 << 5) + __ffs(rem) - 1;
                    float2 nb = s45f[nxt];
                    contS += 0.5f * (fabsf(a.x - nb.x) + fabsf(a.y - nb.y));
                } else {
                    g_last_p45[rs] = a;          // unique last valid in segment
                }
            }
        }
        if (tid == 0) {
            int f = SEG;
#pragma unroll
            for (int k = 15; k >= 0; k--)
                if (smask[k]) f = (k << 5) + __ffs(smask[k]) - 1;
            g_first_idx[rs] = f;
            if (f < SEG) g_first_p45[rs] = s45f[f];
        }

        s0 = s1;
    }

    // ---- drain any remaining recon iterations ----
    for (; rcur < n4; rcur += rstep) {
        float4 r = r4[rcur], m = i4[rcur];
        float dx = r.x - m.x, dy = r.y - m.y, dz = r.z - m.z, dw = r.w - m.w;
        reconS += dx * dx + dy * dy + dz * dz + dw * dw;
    }

    // ---- block reduce + global atomic accumulate ----
    float vals[6] = {coordS, widthS, bceS, nvS, contS, reconS};
#pragma unroll
    for (int q = 0; q < 6; q++) {
        float v = warpReduceSumF(vals[q]);
        if (lane == 0) swred[q][wid] = v;
    }
    __syncthreads();
    if (wid == 0 && lane < 6) {
        float v = 0.f;
#pragma unroll
        for (int j = 0; j < 8; j++) v += swred[lane][j];
        atomicAdd(&g_acc[lane], v);
    }
    __syncthreads();

    // ---- last-block finalize ----
    if (tid == 0) {
        __threadfence();   // release: publishes this block's writes (cumulative)
        unsigned int t = atomicAdd(&g_ticket, 1u);
        slast = (t == (unsigned int)(NBLOCKS - 1)) ? 1 : 0;
    }
    __syncthreads();
    if (!slast) return;
    __threadfence();       // acquire (single block)

    // cross-segment continuity fixup: one row per thread, prefetched loads
    float fix = 0.f;
    for (int r = tid; r < B; r += TPB) {
        int    fidx[SEGS];
        float2 fp[SEGS], lp[SEGS];
#pragma unroll
        for (int s = 0; s < SEGS; s++) {
            int q = r * SEGS + s;
            fidx[s] = g_first_idx[q];
            fp[s]   = g_first_p45[q];
            lp[s]   = g_last_p45[q];
        }
        float2 nf = make_float2(0.f, 0.f);
        bool have = false;
#pragma unroll
        for (int s = SEGS - 1; s >= 0; s--) {
            if (fidx[s] < SEG) {
                if (have) fix += 0.5f * (fabsf(lp[s].x - nf.x) + fabsf(lp[s].y - nf.y));
                nf = fp[s];
                have = true;
            }
        }
    }
    {
        float v = warpReduceSumF(fix);
        if (lane == 0) swred[0][wid] = v;
    }
    __syncthreads();
    if (tid == 0) {
        float fsum = 0.f;
#pragma unroll
        for (int j = 0; j < 8; j++) fsum += swred[0][j];

        double t0 = (double)g_acc[0], t1 = (double)g_acc[1], t2 = (double)g_acc[2];
        double nv = (double)g_acc[3];
        double t4 = (double)g_acc[4] + (double)fsum;
        double t5 = (double)g_acc[5];

        double coord    = (nv > 0.0) ? t0 / fmax(nv * 6.0, 1.0) : 0.0;
        double width    = (nv > 0.0) ? t1 / fmax(nv * 2.0, 1.0) : 0.0;
        double validity = t2 / ((double)B * (double)M_ROW);
        double cont     = t4 / (double)B;
        double recon    = t5 / (double)nrec;
        out[0] = (float)(coord + width + 2.0 * validity + 0.2 * cont + 0.1 * recon);

        // self-reset for the next graph replay
        g_ticket = 0u;
        g_work   = 0u;
#pragma unroll
        for (int q = 0; q < 6; q++) g_acc[q] = 0.f;
        __threadfence();
    }
}

extern "C" void kernel_launch(void* const* d_in, const int* in_sizes, int n_in,
                              void* d_out, int out_size)
{
    const float* preds = (const float*)d_in[0];
    const float* tgts  = (const float*)d_in[1];
    const float* rec   = (const float*)d_in[2];
    const float* img   = (const float*)d_in[3];

    const int B    = in_sizes[0] / (M_ROW * 9);
    const int nrec = in_sizes[2];

    loss_fused_kernel<<<NBLOCKS, TPB>>>(preds, tgts, rec, img,
                                        (float*)d_out, B, nrec);
}